// round 2
// baseline (speedup 1.0000x reference)
#include <cuda_runtime.h>
#include <cuda_bf16.h>
#include <math.h>

#define SEQ   2048
#define DIM   2048
#define HEADS 16
#define DHEAD 128
#define EPSV  1e-5f
#define MASKV 1e-10f
#define QSCALE 0.08838834764831845f  /* 128^-0.5 */

// ---------------- scratch (device globals; no allocation allowed) ----------------
__device__ float g_xn[SEQ * DIM];            // 16 MB
__device__ float g_q [SEQ * DIM];            // 16 MB  (layout [i][h*128+d])
__device__ float g_k [SEQ * DHEAD];          // 1 MB
__device__ float g_v [SEQ * DHEAD];          // 1 MB
__device__ float g_suf[(SEQ + 1) * DHEAD];   // suffix sums of V
__device__ float g_o [SEQ * DIM];            // attention output [i][h*128+d]

// ---------------- RMSNorm ----------------
__global__ void rmsnorm_kernel(const float* __restrict__ x,
                               const float* __restrict__ gamma,
                               float* __restrict__ xn) {
    int row = blockIdx.x;
    int tid = threadIdx.x;
    const float4* xr = (const float4*)(x + (size_t)row * DIM);
    const float4* g4 = (const float4*)gamma;
    __shared__ float red[256];
    float4 vals[2];
    float s = 0.f;
    #pragma unroll
    for (int it = 0; it < 2; it++) {
        float4 v = xr[tid + it * 256];
        vals[it] = v;
        s += v.x * v.x + v.y * v.y + v.z * v.z + v.w * v.w;
    }
    red[tid] = s;
    __syncthreads();
    for (int o = 128; o > 0; o >>= 1) {
        if (tid < o) red[tid] += red[tid + o];
        __syncthreads();
    }
    float inv = 1.0f / sqrtf(red[0] / (float)DIM + EPSV);
    float4* outr = (float4*)(xn + (size_t)row * DIM);
    #pragma unroll
    for (int it = 0; it < 2; it++) {
        float4 v = vals[it];
        float4 g = g4[tid + it * 256];
        v.x = (inv * v.x) * g.x;
        v.y = (inv * v.y) * g.y;
        v.z = (inv * v.z) * g.z;
        v.w = (inv * v.w) * g.w;
        outr[tid + it * 256] = v;
    }
}

// ---------------- fp32 SGEMM: C[M,N] = A[M,K] @ B[K,N] (all row-major) ----------------
#define BM 128
#define BN 128
#define BKG 16
__global__ void sgemm_kernel(const float* __restrict__ A,
                             const float* __restrict__ B,
                             float* __restrict__ C,
                             int M, int N, int K) {
    __shared__ float As[BKG][BM];
    __shared__ float Bs[BKG][BN];
    int bx = blockIdx.x, by = blockIdx.y;
    int tid = threadIdx.x;
    int tx = tid % 16, ty = tid / 16;

    int arow = tid / 4;            // 0..63
    int acol = (tid % 4) * 4;      // 0,4,8,12
    int brow = tid / 32;           // 0..7
    int bcol = (tid % 32) * 4;

    const float* Ab = A + (size_t)(by * BM) * K;
    const float* Bb = B + bx * BN;

    float acc[8][8];
    #pragma unroll
    for (int i = 0; i < 8; i++)
        #pragma unroll
        for (int j = 0; j < 8; j++) acc[i][j] = 0.f;

    for (int k0 = 0; k0 < K; k0 += BKG) {
        #pragma unroll
        for (int i = 0; i < 2; i++) {
            int r = arow + i * 64;
            float4 a = *(const float4*)(Ab + (size_t)r * K + k0 + acol);
            As[acol + 0][r] = a.x;
            As[acol + 1][r] = a.y;
            As[acol + 2][r] = a.z;
            As[acol + 3][r] = a.w;
        }
        #pragma unroll
        for (int i = 0; i < 2; i++) {
            int r = brow + i * 8;
            *(float4*)(&Bs[r][bcol]) = *(const float4*)(Bb + (size_t)(k0 + r) * N + bcol);
        }
        __syncthreads();
        #pragma unroll
        for (int kk = 0; kk < BKG; kk++) {
            float4 a0 = *(const float4*)(&As[kk][ty * 8]);
            float4 a1 = *(const float4*)(&As[kk][ty * 8 + 4]);
            float4 b0 = *(const float4*)(&Bs[kk][tx * 8]);
            float4 b1 = *(const float4*)(&Bs[kk][tx * 8 + 4]);
            float ra[8] = {a0.x, a0.y, a0.z, a0.w, a1.x, a1.y, a1.z, a1.w};
            float rb[8] = {b0.x, b0.y, b0.z, b0.w, b1.x, b1.y, b1.z, b1.w};
            #pragma unroll
            for (int i = 0; i < 8; i++)
                #pragma unroll
                for (int j = 0; j < 8; j++) acc[i][j] += ra[i] * rb[j];
        }
        __syncthreads();
    }
    float* Cb = C + (size_t)(by * BM + ty * 8) * N + bx * BN + tx * 8;
    #pragma unroll
    for (int i = 0; i < 8; i++) {
        *(float4*)(Cb + (size_t)i * N)     = make_float4(acc[i][0], acc[i][1], acc[i][2], acc[i][3]);
        *(float4*)(Cb + (size_t)i * N + 4) = make_float4(acc[i][4], acc[i][5], acc[i][6], acc[i][7]);
    }
}

// ---------------- suffix sums of V over sequence ----------------
__global__ void suffix_kernel(const float* __restrict__ v, float* __restrict__ suf) {
    int d = threadIdx.x;   // 128
    float a = 0.f;
    suf[(size_t)SEQ * DHEAD + d] = 0.f;
    for (int j = SEQ - 1; j >= 0; j--) {
        a += v[(size_t)j * DHEAD + d];
        suf[(size_t)j * DHEAD + d] = a;
    }
}

// ---------------- causal attention with analytic masked tail ----------------
// grid: (qb=SEQ/64, h=16), block 256.  Thread (tx,ty): rows ty*4+r, S-cols tx*4+c, V-cols tx*8+c
#define KLD 68   /* k_s leading dim (transposed [d][j]) */
#define PLD 65   /* p_s leading dim */
__global__ void attn_kernel(const float* __restrict__ q,
                            const float* __restrict__ kmat,
                            const float* __restrict__ vmat,
                            const float* __restrict__ bias,
                            const float* __restrict__ suf,
                            float* __restrict__ O) {
    extern __shared__ float sm[];
    float* q_s = sm;                        // [64][128]
    float* k_s = q_s + 64 * 128;            // [128][KLD]
    float* v_s = k_s + 128 * KLD;           // [64][128]
    float* p_s = v_s + 64 * 128;            // [64][PLD]

    int qb = blockIdx.x, h = blockIdx.y;
    int i0 = qb * 64;
    int tid = threadIdx.x;
    int tx = tid % 16, ty = tid / 16;

    // load Q tile (pre-scaled)
    for (int it = tid; it < 64 * 32; it += 256) {
        int r = it / 32, c4 = (it % 32) * 4;
        float4 a = *(const float4*)(q + (size_t)(i0 + r) * DIM + h * DHEAD + c4);
        a.x *= QSCALE; a.y *= QSCALE; a.z *= QSCALE; a.w *= QSCALE;
        *(float4*)(q_s + r * 128 + c4) = a;
    }

    float m[4], l[4], acc[4][8];
    #pragma unroll
    for (int r = 0; r < 4; r++) {
        m[r] = -INFINITY; l[r] = 0.f;
        #pragma unroll
        for (int c = 0; c < 8; c++) acc[r][c] = 0.f;
    }

    for (int kb = 0; kb <= qb; kb++) {
        int j0 = kb * 64;
        __syncthreads();
        // load K (transposed to [d][j]) and V tiles
        for (int it = tid; it < 64 * 32; it += 256) {
            int r = it / 32, c4 = (it % 32) * 4;
            float4 a = *(const float4*)(kmat + (size_t)(j0 + r) * DHEAD + c4);
            k_s[(c4 + 0) * KLD + r] = a.x;
            k_s[(c4 + 1) * KLD + r] = a.y;
            k_s[(c4 + 2) * KLD + r] = a.z;
            k_s[(c4 + 3) * KLD + r] = a.w;
            *(float4*)(v_s + r * 128 + c4) = *(const float4*)(vmat + (size_t)(j0 + r) * DHEAD + c4);
        }
        __syncthreads();

        // S = Q K^T  (4x4 per thread)
        float s[4][4];
        #pragma unroll
        for (int r = 0; r < 4; r++)
            #pragma unroll
            for (int c = 0; c < 4; c++) s[r][c] = 0.f;
        #pragma unroll 2
        for (int d = 0; d < 128; d += 4) {
            float qreg[4][4];
            #pragma unroll
            for (int r = 0; r < 4; r++) {
                float4 t = *(const float4*)(q_s + (ty * 4 + r) * 128 + d);
                qreg[r][0] = t.x; qreg[r][1] = t.y; qreg[r][2] = t.z; qreg[r][3] = t.w;
            }
            #pragma unroll
            for (int dd = 0; dd < 4; dd++) {
                float4 t = *(const float4*)(k_s + (d + dd) * KLD + tx * 4);
                float kc[4] = {t.x, t.y, t.z, t.w};
                #pragma unroll
                for (int r = 0; r < 4; r++)
                    #pragma unroll
                    for (int c = 0; c < 4; c++) s[r][c] += qreg[r][dd] * kc[c];
            }
        }

        // + bias, causal mask (only diagonal tile can mask)
        #pragma unroll
        for (int r = 0; r < 4; r++) {
            int i = i0 + ty * 4 + r;
            float4 b4 = *(const float4*)(bias + ((size_t)h * SEQ + i) * SEQ + j0 + tx * 4);
            float bb[4] = {b4.x, b4.y, b4.z, b4.w};
            #pragma unroll
            for (int c = 0; c < 4; c++) {
                int j = j0 + tx * 4 + c;
                float val = s[r][c] + bb[c];
                s[r][c] = (j <= i) ? val : -INFINITY;
            }
        }

        // online softmax update
        #pragma unroll
        for (int r = 0; r < 4; r++) {
            float mx = fmaxf(fmaxf(s[r][0], s[r][1]), fmaxf(s[r][2], s[r][3]));
            #pragma unroll
            for (int o = 1; o < 16; o <<= 1)
                mx = fmaxf(mx, __shfl_xor_sync(0xffffffffu, mx, o));
            float mnew = fmaxf(m[r], mx);
            float alpha = expf(m[r] - mnew);
            float p0 = expf(s[r][0] - mnew);
            float p1 = expf(s[r][1] - mnew);
            float p2 = expf(s[r][2] - mnew);
            float p3 = expf(s[r][3] - mnew);
            float rs = p0 + p1 + p2 + p3;
            #pragma unroll
            for (int o = 1; o < 16; o <<= 1)
                rs += __shfl_xor_sync(0xffffffffu, rs, o);
            l[r] = l[r] * alpha + rs;
            m[r] = mnew;
            #pragma unroll
            for (int c = 0; c < 8; c++) acc[r][c] *= alpha;
            float* pr = p_s + (ty * 4 + r) * PLD + tx * 4;
            pr[0] = p0; pr[1] = p1; pr[2] = p2; pr[3] = p3;
        }
        __syncthreads();

        // acc += P @ V
        #pragma unroll 2
        for (int j = 0; j < 64; j++) {
            float pv[4];
            #pragma unroll
            for (int r = 0; r < 4; r++) pv[r] = p_s[(ty * 4 + r) * PLD + j];
            float4 v0 = *(const float4*)(v_s + j * 128 + tx * 8);
            float4 v1 = *(const float4*)(v_s + j * 128 + tx * 8 + 4);
            float vv[8] = {v0.x, v0.y, v0.z, v0.w, v1.x, v1.y, v1.z, v1.w};
            #pragma unroll
            for (int r = 0; r < 4; r++)
                #pragma unroll
                for (int c = 0; c < 8; c++) acc[r][c] += pv[r] * vv[c];
        }
    }

    // analytic masked tail (logit = 1e-10 for all j>i), then normalize + store
    #pragma unroll
    for (int r = 0; r < 4; r++) {
        int i = i0 + ty * 4 + r;
        float mnew = fmaxf(m[r], MASKV);
        float alpha = expf(m[r] - mnew);
        float w = expf(MASKV - mnew);
        float cnt = (float)(SEQ - 1 - i);
        float lr = l[r] * alpha + cnt * w;
        float inv = 1.0f / lr;
        const float* sp = suf + (size_t)(i + 1) * DHEAD + tx * 8;
        float4 s0 = *(const float4*)(sp);
        float4 s1 = *(const float4*)(sp + 4);
        float sv[8] = {s0.x, s0.y, s0.z, s0.w, s1.x, s1.y, s1.z, s1.w};
        float o[8];
        #pragma unroll
        for (int c = 0; c < 8; c++) o[c] = (acc[r][c] * alpha + w * sv[c]) * inv;
        float* Ob = O + (size_t)i * DIM + h * DHEAD + tx * 8;
        *(float4*)(Ob)     = make_float4(o[0], o[1], o[2], o[3]);
        *(float4*)(Ob + 4) = make_float4(o[4], o[5], o[6], o[7]);
    }
}

// ---------------- launcher ----------------
extern "C" void kernel_launch(void* const* d_in, const int* in_sizes, int n_in,
                              void* d_out, int out_size) {
    const float* x     = (const float*)d_in[0];
    const float* bias  = (const float*)d_in[1];
    const float* gamma = (const float*)d_in[2];
    const float* wq    = (const float*)d_in[3];
    const float* wk    = (const float*)d_in[4];
    const float* wv    = (const float*)d_in[5];
    const float* wo    = (const float*)d_in[6];
    float* out = (float*)d_out;

    float *xn, *q, *k, *v, *suf, *o;
    cudaGetSymbolAddress((void**)&xn,  g_xn);
    cudaGetSymbolAddress((void**)&q,   g_q);
    cudaGetSymbolAddress((void**)&k,   g_k);
    cudaGetSymbolAddress((void**)&v,   g_v);
    cudaGetSymbolAddress((void**)&suf, g_suf);
    cudaGetSymbolAddress((void**)&o,   g_o);

    rmsnorm_kernel<<<SEQ, 256>>>(x, gamma, xn);
    sgemm_kernel<<<dim3(DIM / BN, SEQ / BM), 256>>>(xn, wq, q, SEQ, DIM, DIM);
    sgemm_kernel<<<dim3(DHEAD / BN, SEQ / BM), 256>>>(xn, wk, k, SEQ, DHEAD, DIM);
    sgemm_kernel<<<dim3(DHEAD / BN, SEQ / BM), 256>>>(xn, wv, v, SEQ, DHEAD, DIM);
    suffix_kernel<<<1, 128>>>(v, suf);

    size_t smem = (size_t)(64 * 128 + 128 * KLD + 64 * 128 + 64 * PLD) * sizeof(float);
    cudaFuncSetAttribute(attn_kernel, cudaFuncAttributeMaxDynamicSharedMemorySize, (int)smem);
    attn_kernel<<<dim3(SEQ / 64, HEADS), 256, smem>>>(q, k, v, bias, suf, o);

    sgemm_kernel<<<dim3(DIM / BN, SEQ / BM), 256>>>(o, wo, out, SEQ, DIM, DIM);
}

// round 4
// speedup vs baseline: 1.3120x; 1.3120x over previous
#include <cuda_runtime.h>
#include <cuda_bf16.h>
#include <math.h>
#include <stdint.h>

#define SEQ   2048
#define DIM   2048
#define HEADS 16
#define DHEAD 128
#define EPSV  1e-5f
#define MASKV 1e-10f
#define QSCALE 0.08838834764831845f  /* 128^-0.5 */

// ---------------- scratch (device globals; no allocation allowed) ----------------
__device__ float g_xn[SEQ * DIM];            // 16 MB
__device__ float g_q [SEQ * DIM];            // 16 MB  (layout [i][h*128+d])
__device__ float g_k [SEQ * DHEAD];          // 1 MB
__device__ float g_v [SEQ * DHEAD];          // 1 MB
__device__ float g_suf[(SEQ + 1) * DHEAD];   // suffix sums of V
__device__ float g_o [SEQ * DIM];            // attention output [i][h*128+d]
__device__ float g_csum[32 * DHEAD];         // suffix-scan partials

// ================= helpers =================
__device__ __forceinline__ uint32_t smem_u32(const void* p) {
    uint32_t a;
    asm("{ .reg .u64 t; cvta.to.shared.u64 t, %1; cvt.u32.u64 %0, t; }" : "=r"(a) : "l"(p));
    return a;
}
__device__ __forceinline__ void ldsm_x4(uint32_t* r, uint32_t addr) {
    asm volatile("ldmatrix.sync.aligned.m8n8.x4.shared.b16 {%0,%1,%2,%3}, [%4];"
                 : "=r"(r[0]), "=r"(r[1]), "=r"(r[2]), "=r"(r[3]) : "r"(addr));
}
__device__ __forceinline__ void ldsm_x2(uint32_t* r, uint32_t addr) {
    asm volatile("ldmatrix.sync.aligned.m8n8.x2.shared.b16 {%0,%1}, [%2];"
                 : "=r"(r[0]), "=r"(r[1]) : "r"(addr));
}
__device__ __forceinline__ void mma_bf16(float* c, const uint32_t* a, const uint32_t* b) {
    asm volatile(
        "mma.sync.aligned.m16n8k16.row.col.f32.bf16.bf16.f32 "
        "{%0,%1,%2,%3}, {%4,%5,%6,%7}, {%8,%9}, {%0,%1,%2,%3};"
        : "+f"(c[0]), "+f"(c[1]), "+f"(c[2]), "+f"(c[3])
        : "r"(a[0]), "r"(a[1]), "r"(a[2]), "r"(a[3]), "r"(b[0]), "r"(b[1]));
}
__device__ __forceinline__ void split2(float x, float y, uint32_t& h, uint32_t& l) {
    __nv_bfloat16 hx = __float2bfloat16(x), hy = __float2bfloat16(y);
    __nv_bfloat16 lx = __float2bfloat16(x - __bfloat162float(hx));
    __nv_bfloat16 ly = __float2bfloat16(y - __bfloat162float(hy));
    h = (uint32_t)__bfloat16_as_ushort(hx) | ((uint32_t)__bfloat16_as_ushort(hy) << 16);
    l = (uint32_t)__bfloat16_as_ushort(lx) | ((uint32_t)__bfloat16_as_ushort(ly) << 16);
}

// ================= bf16x3 mma.sync GEMM =================
// C[128,128] tile = A[M,2048] @ B[2048,N].  A row-major lda=2048, B row-major.
// bx<16 -> Bq/Cq column tile bx; bx==16 -> Bk/Ck; bx==17 -> Bv/Cv.
#define MLDA 40   /* bf16 leading dim (32 data + 8 pad) */

__global__ __launch_bounds__(256, 1) void mm_mma_kernel(
    const float* __restrict__ A,
    const float* __restrict__ Bq, const float* __restrict__ Bk, const float* __restrict__ Bv,
    float* __restrict__ Cq, float* __restrict__ Ck, float* __restrict__ Cv, int Nq)
{
    __shared__ __align__(16) __nv_bfloat16 sAh[128 * MLDA];
    __shared__ __align__(16) __nv_bfloat16 sAl[128 * MLDA];
    __shared__ __align__(16) __nv_bfloat16 sBh[128 * MLDA];
    __shared__ __align__(16) __nv_bfloat16 sBl[128 * MLDA];

    int tid = threadIdx.x;
    int lane = tid & 31, w = tid >> 5;
    int bx = blockIdx.x, by = blockIdx.y;

    const float* B; float* C; int ldb, ldc, n0;
    if (bx < 16)       { B = Bq; C = Cq; ldb = Nq;  ldc = Nq;  n0 = bx * 128; }
    else if (bx == 16) { B = Bk; C = Ck; ldb = 128; ldc = 128; n0 = 0; }
    else               { B = Bv; C = Cv; ldb = 128; ldc = 128; n0 = 0; }
    int m0 = by * 128;

    // warp tile: 64 rows x 32 cols
    int wm = (w & 1) * 64, wn = (w >> 1) * 32;

    uint32_t ah_base = smem_u32(sAh), al_base = smem_u32(sAl);
    uint32_t bh_base = smem_u32(sBh), bl_base = smem_u32(sBl);

    // per-thread gmem load indices (4 float4 each for A and B)
    int am[4], ak[4], bk_[4], bn[4];
    #pragma unroll
    for (int j = 0; j < 4; j++) {
        int it = tid + j * 256;
        am[j] = it >> 3;  ak[j] = (it & 7) * 4;     // A: 128 rows x 8 float4
        bk_[j] = it >> 5; bn[j] = (it & 31) * 4;    // B: 32 k-rows x 32 float4
    }

    float acc[4][4][4];
    #pragma unroll
    for (int mt = 0; mt < 4; mt++)
        #pragma unroll
        for (int nt = 0; nt < 4; nt++)
            #pragma unroll
            for (int i = 0; i < 4; i++) acc[mt][nt][i] = 0.f;

    float4 rA[4], rB[4];
    // prologue load: chunk 0
    #pragma unroll
    for (int j = 0; j < 4; j++) {
        rA[j] = *(const float4*)(A + (size_t)(m0 + am[j]) * 2048 + ak[j]);
        rB[j] = *(const float4*)(B + (size_t)bk_[j] * ldb + n0 + bn[j]);
    }

    for (int c = 0; c < 64; c++) {
        // ---- split + store current chunk to smem ----
        #pragma unroll
        for (int j = 0; j < 4; j++) {
            uint32_t h0, l0, h1, l1;
            split2(rA[j].x, rA[j].y, h0, l0);
            split2(rA[j].z, rA[j].w, h1, l1);
            *(uint2*)&sAh[am[j] * MLDA + ak[j]] = make_uint2(h0, h1);
            *(uint2*)&sAl[am[j] * MLDA + ak[j]] = make_uint2(l0, l1);
            float bv4[4] = {rB[j].x, rB[j].y, rB[j].z, rB[j].w};
            #pragma unroll
            for (int e = 0; e < 4; e++) {
                __nv_bfloat16 hb = __float2bfloat16(bv4[e]);
                __nv_bfloat16 lb = __float2bfloat16(bv4[e] - __bfloat162float(hb));
                sBh[(bn[j] + e) * MLDA + bk_[j]] = hb;
                sBl[(bn[j] + e) * MLDA + bk_[j]] = lb;
            }
        }
        __syncthreads();

        // ---- prefetch next chunk ----
        if (c + 1 < 64) {
            int k0n = (c + 1) * 32;
            #pragma unroll
            for (int j = 0; j < 4; j++) {
                rA[j] = *(const float4*)(A + (size_t)(m0 + am[j]) * 2048 + k0n + ak[j]);
                rB[j] = *(const float4*)(B + (size_t)(k0n + bk_[j]) * ldb + n0 + bn[j]);
            }
        }

        // ---- mma on current chunk: 2 k16 slices x 3 terms ----
        #pragma unroll
        for (int ks = 0; ks < 32; ks += 16) {
            uint32_t fah[4][4], fal[4][4], fbh[4][2], fbl[4][2];
            uint32_t aoff = (uint32_t)(((wm + (lane & 15)) * MLDA + ks + (lane >> 4) * 8) * 2);
            #pragma unroll
            for (int mt = 0; mt < 4; mt++) {
                uint32_t o = aoff + (uint32_t)(mt * 16 * MLDA * 2);
                ldsm_x4(fah[mt], ah_base + o);
                ldsm_x4(fal[mt], al_base + o);
            }
            uint32_t boff = (uint32_t)(((wn + (lane & 7)) * MLDA + ks + ((lane >> 3) & 1) * 8) * 2);
            #pragma unroll
            for (int nt = 0; nt < 4; nt++) {
                uint32_t o = boff + (uint32_t)(nt * 8 * MLDA * 2);
                ldsm_x2(fbh[nt], bh_base + o);
                ldsm_x2(fbl[nt], bl_base + o);
            }
            #pragma unroll
            for (int mt = 0; mt < 4; mt++)
                #pragma unroll
                for (int nt = 0; nt < 4; nt++) {
                    mma_bf16(acc[mt][nt], fah[mt], fbh[nt]);
                    mma_bf16(acc[mt][nt], fah[mt], fbl[nt]);
                    mma_bf16(acc[mt][nt], fal[mt], fbh[nt]);
                }
        }
        __syncthreads();
    }

    // ---- epilogue: fragment -> gmem fp32 ----
    #pragma unroll
    for (int mt = 0; mt < 4; mt++) {
        int row = m0 + wm + mt * 16 + (lane >> 2);
        #pragma unroll
        for (int nt = 0; nt < 4; nt++) {
            int col = n0 + wn + nt * 8 + (lane & 3) * 2;
            *(float2*)(C + (size_t)row * ldc + col)       = make_float2(acc[mt][nt][0], acc[mt][nt][1]);
            *(float2*)(C + (size_t)(row + 8) * ldc + col) = make_float2(acc[mt][nt][2], acc[mt][nt][3]);
        }
    }
}

// ---------------- RMSNorm ----------------
__global__ void rmsnorm_kernel(const float* __restrict__ x,
                               const float* __restrict__ gamma,
                               float* __restrict__ xn) {
    int row = blockIdx.x;
    int tid = threadIdx.x;
    const float4* xr = (const float4*)(x + (size_t)row * DIM);
    const float4* g4 = (const float4*)gamma;
    __shared__ float red[256];
    float4 vals[2];
    float s = 0.f;
    #pragma unroll
    for (int it = 0; it < 2; it++) {
        float4 v = xr[tid + it * 256];
        vals[it] = v;
        s += v.x * v.x + v.y * v.y + v.z * v.z + v.w * v.w;
    }
    red[tid] = s;
    __syncthreads();
    for (int o = 128; o > 0; o >>= 1) {
        if (tid < o) red[tid] += red[tid + o];
        __syncthreads();
    }
    float inv = 1.0f / sqrtf(red[0] / (float)DIM + EPSV);
    float4* outr = (float4*)(xn + (size_t)row * DIM);
    #pragma unroll
    for (int it = 0; it < 2; it++) {
        float4 v = vals[it];
        float4 g = g4[tid + it * 256];
        v.x = (inv * v.x) * g.x;
        v.y = (inv * v.y) * g.y;
        v.z = (inv * v.z) * g.z;
        v.w = (inv * v.w) * g.w;
        outr[tid + it * 256] = v;
    }
}

// ---------------- parallel suffix sums of V ----------------
__global__ void suffix1_kernel(const float* __restrict__ v) {
    int b = blockIdx.x, d = threadIdx.x;
    float a = 0.f;
    for (int j = 0; j < 64; j++) a += v[(size_t)(b * 64 + j) * DHEAD + d];
    g_csum[b * DHEAD + d] = a;
}
__global__ void suffix2_kernel(const float* __restrict__ v, float* __restrict__ suf) {
    int b = blockIdx.x, d = threadIdx.x;
    float tail = 0.f;
    for (int t = b + 1; t < 32; t++) tail += g_csum[t * DHEAD + d];
    if (b == 31) suf[(size_t)SEQ * DHEAD + d] = 0.f;
    float a = tail;
    for (int j = 63; j >= 0; j--) {
        a += v[(size_t)(b * 64 + j) * DHEAD + d];
        suf[(size_t)(b * 64 + j) * DHEAD + d] = a;
    }
}

// ---------------- causal attention with analytic masked tail ----------------
#define KLD 68
#define PLD 65
__global__ void attn_kernel(const float* __restrict__ q,
                            const float* __restrict__ kmat,
                            const float* __restrict__ vmat,
                            const float* __restrict__ bias,
                            const float* __restrict__ suf,
                            float* __restrict__ O) {
    extern __shared__ float sm[];
    float* q_s = sm;
    float* k_s = q_s + 64 * 128;
    float* v_s = k_s + 128 * KLD;
    float* p_s = v_s + 64 * 128;

    int qb = blockIdx.x, h = blockIdx.y;
    int i0 = qb * 64;
    int tid = threadIdx.x;
    int tx = tid % 16, ty = tid / 16;

    for (int it = tid; it < 64 * 32; it += 256) {
        int r = it / 32, c4 = (it % 32) * 4;
        float4 a = *(const float4*)(q + (size_t)(i0 + r) * DIM + h * DHEAD + c4);
        a.x *= QSCALE; a.y *= QSCALE; a.z *= QSCALE; a.w *= QSCALE;
        *(float4*)(q_s + r * 128 + c4) = a;
    }

    float m[4], l[4], acc[4][8];
    #pragma unroll
    for (int r = 0; r < 4; r++) {
        m[r] = -INFINITY; l[r] = 0.f;
        #pragma unroll
        for (int c = 0; c < 8; c++) acc[r][c] = 0.f;
    }

    for (int kb = 0; kb <= qb; kb++) {
        int j0 = kb * 64;
        __syncthreads();
        for (int it = tid; it < 64 * 32; it += 256) {
            int r = it / 32, c4 = (it % 32) * 4;
            float4 a = *(const float4*)(kmat + (size_t)(j0 + r) * DHEAD + c4);
            k_s[(c4 + 0) * KLD + r] = a.x;
            k_s[(c4 + 1) * KLD + r] = a.y;
            k_s[(c4 + 2) * KLD + r] = a.z;
            k_s[(c4 + 3) * KLD + r] = a.w;
            *(float4*)(v_s + r * 128 + c4) = *(const float4*)(vmat + (size_t)(j0 + r) * DHEAD + c4);
        }
        __syncthreads();

        float s[4][4];
        #pragma unroll
        for (int r = 0; r < 4; r++)
            #pragma unroll
            for (int c = 0; c < 4; c++) s[r][c] = 0.f;
        #pragma unroll 2
        for (int d = 0; d < 128; d += 4) {
            float qreg[4][4];
            #pragma unroll
            for (int r = 0; r < 4; r++) {
                float4 t = *(const float4*)(q_s + (ty * 4 + r) * 128 + d);
                qreg[r][0] = t.x; qreg[r][1] = t.y; qreg[r][2] = t.z; qreg[r][3] = t.w;
            }
            #pragma unroll
            for (int dd = 0; dd < 4; dd++) {
                float4 t = *(const float4*)(k_s + (d + dd) * KLD + tx * 4);
                float kc[4] = {t.x, t.y, t.z, t.w};
                #pragma unroll
                for (int r = 0; r < 4; r++)
                    #pragma unroll
                    for (int c = 0; c < 4; c++) s[r][c] += qreg[r][dd] * kc[c];
            }
        }

        #pragma unroll
        for (int r = 0; r < 4; r++) {
            int i = i0 + ty * 4 + r;
            float4 b4 = *(const float4*)(bias + ((size_t)h * SEQ + i) * SEQ + j0 + tx * 4);
            float bb[4] = {b4.x, b4.y, b4.z, b4.w};
            #pragma unroll
            for (int c = 0; c < 4; c++) {
                int j = j0 + tx * 4 + c;
                float val = s[r][c] + bb[c];
                s[r][c] = (j <= i) ? val : -INFINITY;
            }
        }

        #pragma unroll
        for (int r = 0; r < 4; r++) {
            float mx = fmaxf(fmaxf(s[r][0], s[r][1]), fmaxf(s[r][2], s[r][3]));
            #pragma unroll
            for (int o = 1; o < 16; o <<= 1)
                mx = fmaxf(mx, __shfl_xor_sync(0xffffffffu, mx, o));
            float mnew = fmaxf(m[r], mx);
            float alpha = expf(m[r] - mnew);
            float p0 = expf(s[r][0] - mnew);
            float p1 = expf(s[r][1] - mnew);
            float p2 = expf(s[r][2] - mnew);
            float p3 = expf(s[r][3] - mnew);
            float rs = p0 + p1 + p2 + p3;
            #pragma unroll
            for (int o = 1; o < 16; o <<= 1)
                rs += __shfl_xor_sync(0xffffffffu, rs, o);
            l[r] = l[r] * alpha + rs;
            m[r] = mnew;
            #pragma unroll
            for (int c = 0; c < 8; c++) acc[r][c] *= alpha;
            float* pr = p_s + (ty * 4 + r) * PLD + tx * 4;
            pr[0] = p0; pr[1] = p1; pr[2] = p2; pr[3] = p3;
        }
        __syncthreads();

        #pragma unroll 2
        for (int j = 0; j < 64; j++) {
            float pv[4];
            #pragma unroll
            for (int r = 0; r < 4; r++) pv[r] = p_s[(ty * 4 + r) * PLD + j];
            float4 v0 = *(const float4*)(v_s + j * 128 + tx * 8);
            float4 v1 = *(const float4*)(v_s + j * 128 + tx * 8 + 4);
            float vv[8] = {v0.x, v0.y, v0.z, v0.w, v1.x, v1.y, v1.z, v1.w};
            #pragma unroll
            for (int r = 0; r < 4; r++)
                #pragma unroll
                for (int c = 0; c < 8; c++) acc[r][c] += pv[r] * vv[c];
        }
    }

    #pragma unroll
    for (int r = 0; r < 4; r++) {
        int i = i0 + ty * 4 + r;
        float mnew = fmaxf(m[r], MASKV);
        float alpha = expf(m[r] - mnew);
        float w = expf(MASKV - mnew);
        float cnt = (float)(SEQ - 1 - i);
        float lr = l[r] * alpha + cnt * w;
        float inv = 1.0f / lr;
        const float* sp = suf + (size_t)(i + 1) * DHEAD + tx * 8;
        float4 s0 = *(const float4*)(sp);
        float4 s1 = *(const float4*)(sp + 4);
        float sv[8] = {s0.x, s0.y, s0.z, s0.w, s1.x, s1.y, s1.z, s1.w};
        float o[8];
        #pragma unroll
        for (int c = 0; c < 8; c++) o[c] = (acc[r][c] * alpha + w * sv[c]) * inv;
        float* Ob = O + (size_t)i * DIM + h * DHEAD + tx * 8;
        *(float4*)(Ob)     = make_float4(o[0], o[1], o[2], o[3]);
        *(float4*)(Ob + 4) = make_float4(o[4], o[5], o[6], o[7]);
    }
}

// ---------------- launcher ----------------
extern "C" void kernel_launch(void* const* d_in, const int* in_sizes, int n_in,
                              void* d_out, int out_size) {
    const float* x     = (const float*)d_in[0];
    const float* bias  = (const float*)d_in[1];
    const float* gamma = (const float*)d_in[2];
    const float* wq    = (const float*)d_in[3];
    const float* wk    = (const float*)d_in[4];
    const float* wv    = (const float*)d_in[5];
    const float* wo    = (const float*)d_in[6];
    float* out = (float*)d_out;

    float *xn, *q, *k, *v, *suf, *o;
    cudaGetSymbolAddress((void**)&xn,  g_xn);
    cudaGetSymbolAddress((void**)&q,   g_q);
    cudaGetSymbolAddress((void**)&k,   g_k);
    cudaGetSymbolAddress((void**)&v,   g_v);
    cudaGetSymbolAddress((void**)&suf, g_suf);
    cudaGetSymbolAddress((void**)&o,   g_o);

    rmsnorm_kernel<<<SEQ, 256>>>(x, gamma, xn);
    // fused Q/K/V projections: bx 0..15 -> Q column tiles, 16 -> K, 17 -> V
    mm_mma_kernel<<<dim3(18, 16), 256>>>(xn, wq, wk, wv, q, k, v, DIM);
    suffix1_kernel<<<32, 128>>>(v);
    suffix2_kernel<<<32, 128>>>(v, suf);

    size_t smemA = (size_t)(64 * 128 + 128 * KLD + 64 * 128 + 64 * PLD) * sizeof(float);
    cudaFuncSetAttribute(attn_kernel, cudaFuncAttributeMaxDynamicSharedMemorySize, (int)smemA);
    attn_kernel<<<dim3(SEQ / 64, HEADS), 256, smemA>>>(q, k, v, bias, suf, o);

    // O projection
    mm_mma_kernel<<<dim3(16, 16), 256>>>(o, wo, nullptr, nullptr, out, nullptr, nullptr, DIM);
}